// round 12
// baseline (speedup 1.0000x reference)
#include <cuda_runtime.h>
#include <cuda_fp16.h>
#include <mma.h>
#include <math.h>
#include <cstdint>

using namespace nvcuda;

// Problem constants
static constexpr int NN   = 10000;
static constexpr int EE   = 320000;
static constexpr int EN   = EE + NN;        // edges + self loops
static constexpr int IND  = 512;
static constexpr int HIDD = 128;
static constexpr int OUTD = 128;
static constexpr int HEADS = 4;
static constexpr int GC    = 64;
static constexpr int FEAT  = HEADS * GC;    // 256
static constexpr float NEG_SLOPE = 0.2f;
static constexpr int MAXDEG = 256;
static constexpr int SCAN_BLKS = 40;

// -------- scratch (device globals: no allocation allowed) --------
__device__ __half d_h1h[(size_t)NN * HIDD];
__device__ __half d_h1l[(size_t)NN * HIDD];
__device__ __half d_h2h[(size_t)NN * OUTD];
__device__ __half d_h2l[(size_t)NN * OUTD];
__device__ __half d_g16[(size_t)NN * FEAT];
__device__ float  d_asrc[NN * HEADS];
__device__ float  d_adst[NN * HEADS];
__device__ int    d_cnt[NN];          // zero-init; count fills, fill drains to 0
__device__ int    d_off[NN + 1];
__device__ int    d_bsum[SCAN_BLKS];
__device__ int    d_src_csr[EN];
__device__ int    d_is64;

// -------- helpers --------
__device__ __forceinline__ void load_edge(const void* ei, int is64, int tid,
                                          int& s, int& d) {
    if (tid < EE) {
        if (is64) {
            const long long* p = (const long long*)ei;
            s = (int)p[tid];
            d = (int)p[EE + tid];
        } else {
            const int* p = (const int*)ei;
            s = p[tid];
            d = p[EE + tid];
        }
    } else {
        s = d = tid - EE;
    }
}

__device__ __forceinline__ uint32_t h2u(__half2 h) {
    union { __half2 h; uint32_t u; } c; c.h = h; return c.u;
}

// split 4 floats into 2x half2 (hi) + 2x half2 (lo residual)
__device__ __forceinline__ void split_f4(float4 v, uint32_t& hA, uint32_t& hB,
                                         uint32_t& lA, uint32_t& lB) {
    __half hx = __float2half_rn(v.x), hy = __float2half_rn(v.y);
    __half hz = __float2half_rn(v.z), hw = __float2half_rn(v.w);
    hA = h2u(__halves2half2(hx, hy));
    hB = h2u(__halves2half2(hz, hw));
    lA = h2u(__floats2half2_rn(v.x - __half2float(hx), v.y - __half2float(hy)));
    lB = h2u(__floats2half2_rn(v.z - __half2float(hz), v.w - __half2float(hw)));
}

// -------- setup: detect int64 vs int32 edge_index --------
__global__ void setup_kernel(const int* ei) {
    if (threadIdx.x == 0) {
        int ok64 = 1;
        for (int i = 1; i < 256; i += 2)
            if (ei[i] != 0) { ok64 = 0; break; }
        d_is64 = ok64;
    }
}

// -------- CSR build --------
__global__ void count_kernel(const void* __restrict__ ei) {
    int tid = blockIdx.x * blockDim.x + threadIdx.x;
    if (tid >= EN) return;
    int s, d;
    load_edge(ei, d_is64, tid, s, d);
    atomicAdd(&d_cnt[d], 1);
}

__global__ void scanA_kernel() {
    __shared__ int sh[256];
    const int t = threadIdx.x;
    const int idx = blockIdx.x * 256 + t;
    int v = (idx < NN) ? d_cnt[idx] : 0;
    sh[t] = v;
    __syncthreads();
    #pragma unroll
    for (int o = 1; o < 256; o <<= 1) {
        int u = (t >= o) ? sh[t - o] : 0;
        __syncthreads();
        sh[t] += u;
        __syncthreads();
    }
    if (idx < NN) d_off[idx] = sh[t] - v;
    if (t == 255) d_bsum[blockIdx.x] = sh[255];
}

__global__ void scanB_kernel() {
    __shared__ int sh[64];
    const int t = threadIdx.x;
    int v = (t < SCAN_BLKS) ? d_bsum[t] : 0;
    sh[t] = v;
    __syncthreads();
    #pragma unroll
    for (int o = 1; o < 64; o <<= 1) {
        int u = (t >= o) ? sh[t - o] : 0;
        __syncthreads();
        sh[t] += u;
        __syncthreads();
    }
    if (t < SCAN_BLKS) d_bsum[t] = sh[t] - v;
    if (t == 63) d_off[NN] = sh[63];
}

__global__ void scanC_kernel() {
    int idx = blockIdx.x * 256 + threadIdx.x;
    if (idx < NN) d_off[idx] += d_bsum[blockIdx.x];
}

__global__ void fill_kernel(const void* __restrict__ ei) {
    int tid = blockIdx.x * blockDim.x + threadIdx.x;
    if (tid >= EN) return;
    int s, d;
    load_edge(ei, d_is64, tid, s, d);
    int pos = atomicSub(&d_cnt[d], 1) - 1;
    d_src_csr[d_off[d] + pos] = s;
}

// -------- split-fp16 tensor-core GEMM, warp tile 32x32, reg prefetch -------
// C = A@B with A,B given either as fp32 (split on load) or as fp16 hi/lo pair.
// 3-term: Ah@Bh + Ah@Bl + Al@Bh, fp32 accum.
// Tile: BM=64, BN=64, BK=32. 128 threads = 4 warps (2x2 grid of 32x32).
static constexpr int LDA_S = 40;   // 32 + 8 pad (halfs)
static constexpr int LDB_S = 72;   // 64 + 8 pad (halfs)
static constexpr int LDC_S = 68;   // 64 + 4 pad (floats)

__global__ void __launch_bounds__(128) gemm_wmma(
        const float* __restrict__ Af,
        const __half* __restrict__ Ah, const __half* __restrict__ Al,
        const float* __restrict__ Bf,
        const __half* __restrict__ Bh, const __half* __restrict__ Bl,
        const float* __restrict__ bias,
        __half* __restrict__ Oh, __half* __restrict__ Ol,
        int M, int N, int K, int do_relu) {
    __shared__ __align__(16) char sm[19456];
    __half* Ash = (__half*)sm;                    // 64*40 halfs = 5120 B
    __half* Asl = Ash + 64 * LDA_S;               // 5120 B
    __half* Bsh = (__half*)(sm + 10240);          // 32*72 halfs = 4608 B
    __half* Bsl = Bsh + 32 * LDB_S;               // 4608 B
    float*  Cf  = (float*)sm;                     // 64*68*4 = 17408 B (reuse)

    const int t   = threadIdx.x;
    const int wid = t >> 5;
    const int wm  = wid >> 1;         // 0..1
    const int wn  = wid & 1;          // 0..1
    const int m0  = blockIdx.y * 64;
    const int n0  = blockIdx.x * 64;

    // A loader: 64 rows x 32 halfs; 16 halfs/thread
    const int ar = t >> 1;
    const int ac = (t & 1) * 16;
    // B loader: 32 rows x 64 halfs; 16 halfs/thread
    const int br = t >> 2;
    const int bc = (t & 3) * 16;
    const bool aOk = (m0 + ar < M);
    const int  nt  = K / 32;

    uint4 rah[2], ral[2], rbh[2], rbl[2];

    auto load_regs = [&](int k0) {
        if (Af) {
            if (aOk) {
                const float4* p = (const float4*)&Af[(size_t)(m0 + ar) * K + k0 + ac];
                float4 v0 = p[0], v1 = p[1], v2 = p[2], v3 = p[3];
                split_f4(v0, rah[0].x, rah[0].y, ral[0].x, ral[0].y);
                split_f4(v1, rah[0].z, rah[0].w, ral[0].z, ral[0].w);
                split_f4(v2, rah[1].x, rah[1].y, ral[1].x, ral[1].y);
                split_f4(v3, rah[1].z, rah[1].w, ral[1].z, ral[1].w);
            } else {
                rah[0] = rah[1] = ral[0] = ral[1] = make_uint4(0, 0, 0, 0);
            }
        } else {
            if (aOk) {
                const uint4* ph = (const uint4*)&Ah[(size_t)(m0 + ar) * K + k0 + ac];
                const uint4* pl = (const uint4*)&Al[(size_t)(m0 + ar) * K + k0 + ac];
                rah[0] = ph[0]; rah[1] = ph[1];
                ral[0] = pl[0]; ral[1] = pl[1];
            } else {
                rah[0] = rah[1] = ral[0] = ral[1] = make_uint4(0, 0, 0, 0);
            }
        }
        if (Bf) {
            const float4* p = (const float4*)&Bf[(size_t)(k0 + br) * N + n0 + bc];
            float4 v0 = p[0], v1 = p[1], v2 = p[2], v3 = p[3];
            split_f4(v0, rbh[0].x, rbh[0].y, rbl[0].x, rbl[0].y);
            split_f4(v1, rbh[0].z, rbh[0].w, rbl[0].z, rbl[0].w);
            split_f4(v2, rbh[1].x, rbh[1].y, rbl[1].x, rbl[1].y);
            split_f4(v3, rbh[1].z, rbh[1].w, rbl[1].z, rbl[1].w);
        } else {
            const uint4* ph = (const uint4*)&Bh[(size_t)(k0 + br) * N + n0 + bc];
            const uint4* pl = (const uint4*)&Bl[(size_t)(k0 + br) * N + n0 + bc];
            rbh[0] = ph[0]; rbh[1] = ph[1];
            rbl[0] = pl[0]; rbl[1] = pl[1];
        }
    };

    load_regs(0);

    wmma::fragment<wmma::accumulator, 16, 16, 16, float> acc[2][2];
    #pragma unroll
    for (int i = 0; i < 2; i++)
        #pragma unroll
        for (int j = 0; j < 2; j++)
            wmma::fill_fragment(acc[i][j], 0.f);

    for (int tile = 0; tile < nt; tile++) {
        // commit prefetched regs to smem
        *(uint4*)&Ash[ar * LDA_S + ac]     = rah[0];
        *(uint4*)&Ash[ar * LDA_S + ac + 8] = rah[1];
        *(uint4*)&Asl[ar * LDA_S + ac]     = ral[0];
        *(uint4*)&Asl[ar * LDA_S + ac + 8] = ral[1];
        *(uint4*)&Bsh[br * LDB_S + bc]     = rbh[0];
        *(uint4*)&Bsh[br * LDB_S + bc + 8] = rbh[1];
        *(uint4*)&Bsl[br * LDB_S + bc]     = rbl[0];
        *(uint4*)&Bsl[br * LDB_S + bc + 8] = rbl[1];
        __syncthreads();

        if (tile + 1 < nt) load_regs((tile + 1) * 32);

        #pragma unroll
        for (int kk = 0; kk < 32; kk += 16) {
            wmma::fragment<wmma::matrix_b, 16, 16, 16, __half, wmma::row_major> bfh[2], bfl[2];
            #pragma unroll
            for (int ni = 0; ni < 2; ni++) {
                wmma::load_matrix_sync(bfh[ni], &Bsh[kk * LDB_S + wn * 32 + ni * 16], LDB_S);
                wmma::load_matrix_sync(bfl[ni], &Bsl[kk * LDB_S + wn * 32 + ni * 16], LDB_S);
            }
            #pragma unroll
            for (int mi = 0; mi < 2; mi++) {
                wmma::fragment<wmma::matrix_a, 16, 16, 16, __half, wmma::row_major> afh, afl;
                const int ro = (wm * 32 + mi * 16) * LDA_S + kk;
                wmma::load_matrix_sync(afh, &Ash[ro], LDA_S);
                wmma::load_matrix_sync(afl, &Asl[ro], LDA_S);
                #pragma unroll
                for (int ni = 0; ni < 2; ni++) {
                    wmma::mma_sync(acc[mi][ni], afh, bfh[ni], acc[mi][ni]);
                    wmma::mma_sync(acc[mi][ni], afh, bfl[ni], acc[mi][ni]);
                    wmma::mma_sync(acc[mi][ni], afl, bfh[ni], acc[mi][ni]);
                }
            }
        }
        __syncthreads();
    }

    // stage fp32 results to smem (overlays A/B tiles; all MMAs done)
    #pragma unroll
    for (int mi = 0; mi < 2; mi++)
        #pragma unroll
        for (int ni = 0; ni < 2; ni++)
            wmma::store_matrix_sync(
                &Cf[(wm * 32 + mi * 16) * LDC_S + wn * 32 + ni * 16],
                acc[mi][ni], LDC_S, wmma::mem_row_major);
    __syncthreads();

    // epilogue: 128 threads, 32 outputs each
    {
        const int row = t >> 1;
        const int c0  = (t & 1) * 32;
        if (m0 + row < M) {
            #pragma unroll
            for (int j = 0; j < 32; j += 2) {
                float v0 = Cf[row * LDC_S + c0 + j];
                float v1 = Cf[row * LDC_S + c0 + j + 1];
                if (bias) {
                    v0 += bias[n0 + c0 + j];
                    v1 += bias[n0 + c0 + j + 1];
                }
                if (do_relu) { v0 = fmaxf(v0, 0.f); v1 = fmaxf(v1, 0.f); }
                __half h0 = __float2half_rn(v0), h1 = __float2half_rn(v1);
                size_t o = (size_t)(m0 + row) * N + n0 + c0 + j;
                *(__half2*)&Oh[o] = __halves2half2(h0, h1);
                if (Ol)
                    *(__half2*)&Ol[o] = __floats2half2_rn(
                        v0 - __half2float(h0), v1 - __half2float(h1));
            }
        }
    }
}

// -------- attention coefficients from fp16 g: one warp per (node, head) ----
__global__ void attn_coef_kernel(const float* __restrict__ att_src,
                                 const float* __restrict__ att_dst) {
    int warp = (blockIdx.x * blockDim.x + threadIdx.x) >> 5;
    int lane = threadIdx.x & 31;
    if (warp >= NN * HEADS) return;
    int n = warp / HEADS, h = warp % HEADS;
    const __half2* gp = (const __half2*)(d_g16 + (size_t)n * FEAT + h * GC);
    float2 gv = __half22float2(gp[lane]);
    float ss = gv.x * att_src[h * GC + 2 * lane] +
               gv.y * att_src[h * GC + 2 * lane + 1];
    float sd = gv.x * att_dst[h * GC + 2 * lane] +
               gv.y * att_dst[h * GC + 2 * lane + 1];
    #pragma unroll
    for (int o = 16; o; o >>= 1) {
        ss += __shfl_xor_sync(0xFFFFFFFFu, ss, o);
        sd += __shfl_xor_sync(0xFFFFFFFFu, sd, o);
    }
    if (lane == 0) {
        d_asrc[n * HEADS + h] = ss;
        d_adst[n * HEADS + h] = sd;
    }
}

// -------- gather aggregation: two-pass, fp16 features in pass 2 --------
__global__ void __launch_bounds__(256) gather_kernel(float* __restrict__ out,
                                                     const float* __restrict__ bias_g) {
    __shared__ float s_ex[4][MAXDEG * HEADS];
    __shared__ int   s_src[4][MAXDEG];

    const int grp  = threadIdx.x >> 6;
    const int t    = threadIdx.x & 63;
    const int node = blockIdx.x * 4 + grp;
    const int h    = t >> 4;
    const int l16  = t & 15;

    const int beg = d_off[node];
    const int deg = d_off[node + 1] - beg;
    const int cached = (deg < MAXDEG) ? deg : MAXDEG;

    for (int j = t; j < cached; j += 64)
        s_src[grp][j] = d_src_csr[beg + j];
    __syncthreads();

    const float adst_h = d_adst[node * HEADS + h];

    float psum = 0.f;
    for (int j = l16; j < deg; j += 16) {
        int s = (j < MAXDEG) ? s_src[grp][j] : d_src_csr[beg + j];
        float e = d_asrc[s * HEADS + h] + adst_h;
        e = (e > 0.f) ? e : NEG_SLOPE * e;
        float ex = __expf(e);
        if (j < MAXDEG) s_ex[grp][j * HEADS + h] = ex;
        psum += ex;
    }
    #pragma unroll
    for (int o = 8; o; o >>= 1)
        psum += __shfl_xor_sync(0xFFFFFFFFu, psum, o);
    const float inv = __frcp_rn(psum);
    __syncthreads();

    float4 acc = make_float4(0.f, 0.f, 0.f, 0.f);
    #pragma unroll 8
    for (int j = 0; j < cached; j++) {
        float alpha = s_ex[grp][j * HEADS + h] * inv;
        int s = s_src[grp][j];
        const __half2* gp = (const __half2*)&d_g16[(size_t)s * FEAT + 4 * t];
        float2 f01 = __half22float2(gp[0]);
        float2 f23 = __half22float2(gp[1]);
        acc.x = fmaf(f01.x, alpha, acc.x);
        acc.y = fmaf(f01.y, alpha, acc.y);
        acc.z = fmaf(f23.x, alpha, acc.z);
        acc.w = fmaf(f23.y, alpha, acc.w);
    }
    for (int j = cached; j < deg; j++) {
        int s = d_src_csr[beg + j];
        float e = d_asrc[s * HEADS + h] + adst_h;
        e = (e > 0.f) ? e : NEG_SLOPE * e;
        float alpha = __expf(e) * inv;
        const __half2* gp = (const __half2*)&d_g16[(size_t)s * FEAT + 4 * t];
        float2 f01 = __half22float2(gp[0]);
        float2 f23 = __half22float2(gp[1]);
        acc.x = fmaf(f01.x, alpha, acc.x);
        acc.y = fmaf(f01.y, alpha, acc.y);
        acc.z = fmaf(f23.x, alpha, acc.z);
        acc.w = fmaf(f23.y, alpha, acc.w);
    }

    float4 bv = *(const float4*)&bias_g[4 * t];
    acc.x += bv.x; acc.y += bv.y; acc.z += bv.z; acc.w += bv.w;
    *(float4*)&out[(size_t)node * FEAT + 4 * t] = acc;
}

// ----------------------------------------------------------------------------
extern "C" void kernel_launch(void* const* d_in, const int* in_sizes, int n_in,
                              void* d_out, int out_size) {
    const float* x        = (const float*)d_in[0];
    const void*  ei       = d_in[1];
    const float* W1       = (const float*)d_in[2];
    const float* b1       = (const float*)d_in[3];
    const float* W2       = (const float*)d_in[4];
    const float* b2       = (const float*)d_in[5];
    const float* Wg       = (const float*)d_in[6];
    const float* att_src  = (const float*)d_in[7];
    const float* att_dst  = (const float*)d_in[8];
    const float* bias_g   = (const float*)d_in[9];
    float* out = (float*)d_out;

    void *p_h1h, *p_h1l, *p_h2h, *p_h2l, *p_g16;
    cudaGetSymbolAddress(&p_h1h, d_h1h); cudaGetSymbolAddress(&p_h1l, d_h1l);
    cudaGetSymbolAddress(&p_h2h, d_h2h); cudaGetSymbolAddress(&p_h2l, d_h2l);
    cudaGetSymbolAddress(&p_g16, d_g16);

    setup_kernel<<<1, 32>>>((const int*)ei);                             // 0
    count_kernel<<<(EN + 255) / 256, 256>>>(ei);                         // 1
    scanA_kernel<<<SCAN_BLKS, 256>>>();                                  // 2
    {   // 3 (profiled): GEMM1  h1 = relu(x@W1 + b1), fp32 inputs fused-split
        dim3 grid(HIDD / 64, (NN + 63) / 64);
        gemm_wmma<<<grid, 128>>>(x, nullptr, nullptr,
                                 W1, nullptr, nullptr,
                                 b1, (__half*)p_h1h, (__half*)p_h1l,
                                 NN, HIDD, IND, 1);
    }
    scanB_kernel<<<1, 64>>>();                                           // 4
    scanC_kernel<<<SCAN_BLKS, 256>>>();                                  // 5
    fill_kernel<<<(EN + 255) / 256, 256>>>(ei);                          // 6
    {   // 7: GEMM2  h2 = h1@W2 + b2
        dim3 grid(OUTD / 64, (NN + 63) / 64);
        gemm_wmma<<<grid, 128>>>(nullptr, (const __half*)p_h1h, (const __half*)p_h1l,
                                 W2, nullptr, nullptr,
                                 b2, (__half*)p_h2h, (__half*)p_h2l,
                                 NN, OUTD, HIDD, 0);
    }
    {   // 8: GEMM3  g = h2@Wg  (hi only out)
        dim3 grid(FEAT / 64, (NN + 63) / 64);
        gemm_wmma<<<grid, 128>>>(nullptr, (const __half*)p_h2h, (const __half*)p_h2l,
                                 Wg, nullptr, nullptr,
                                 nullptr, (__half*)p_g16, nullptr,
                                 NN, FEAT, OUTD, 0);
    }
    {   // 9
        int warps = NN * HEADS;
        attn_coef_kernel<<<(warps * 32 + 255) / 256, 256>>>(att_src, att_dst);
    }
    gather_kernel<<<NN / 4, 256>>>(out, bias_g);                         // 10
}

// round 13
// speedup vs baseline: 1.0703x; 1.0703x over previous
#include <cuda_runtime.h>
#include <cuda_fp16.h>
#include <mma.h>
#include <math.h>
#include <cstdint>

using namespace nvcuda;

// Problem constants
static constexpr int NN   = 10000;
static constexpr int EE   = 320000;
static constexpr int EN   = EE + NN;        // edges + self loops
static constexpr int IND  = 512;
static constexpr int HIDD = 128;
static constexpr int OUTD = 128;
static constexpr int HEADS = 4;
static constexpr int GC    = 64;
static constexpr int FEAT  = HEADS * GC;    // 256
static constexpr float NEG_SLOPE = 0.2f;
static constexpr int MAXDEG = 256;
static constexpr int SCAN_BLKS = 40;

// -------- scratch (device globals: no allocation allowed) --------
__device__ __half d_xh [(size_t)NN * IND];
__device__ __half d_xl [(size_t)NN * IND];
__device__ __half d_w1h[IND * HIDD];
__device__ __half d_w1l[IND * HIDD];
__device__ __half d_w2h[HIDD * OUTD];
__device__ __half d_w2l[HIDD * OUTD];
__device__ __half d_wgh[OUTD * FEAT];
__device__ __half d_wgl[OUTD * FEAT];
__device__ __half d_h1h[(size_t)NN * HIDD];
__device__ __half d_h1l[(size_t)NN * HIDD];
__device__ __half d_h2h[(size_t)NN * OUTD];
__device__ __half d_h2l[(size_t)NN * OUTD];
__device__ __half d_g16[(size_t)NN * FEAT];
__device__ float  d_asrc[NN * HEADS];
__device__ float  d_adst[NN * HEADS];
__device__ int    d_cnt[NN];          // zero-init; count fills, fill drains to 0
__device__ int    d_off[NN + 1];
__device__ int    d_bsum[SCAN_BLKS];
__device__ int    d_src_csr[EN];
__device__ int    d_is64;

// -------- helpers --------
__device__ __forceinline__ void load_edge(const void* ei, int is64, int tid,
                                          int& s, int& d) {
    if (tid < EE) {
        if (is64) {
            const long long* p = (const long long*)ei;
            s = (int)p[tid];
            d = (int)p[EE + tid];
        } else {
            const int* p = (const int*)ei;
            s = p[tid];
            d = p[EE + tid];
        }
    } else {
        s = d = tid - EE;
    }
}

__device__ __forceinline__ void cp16(uint32_t smem_dst, const void* gsrc, bool pred) {
    int sz = pred ? 16 : 0;
    asm volatile("cp.async.ca.shared.global [%0], [%1], 16, %2;\n"
                 :: "r"(smem_dst), "l"(gsrc), "r"(sz));
}
__device__ __forceinline__ void cp_commit() {
    asm volatile("cp.async.commit_group;\n");
}
__device__ __forceinline__ void cp_wait0() {
    asm volatile("cp.async.wait_group 0;\n");
}

// -------- setup: detect int64 vs int32 edge_index --------
__global__ void setup_kernel(const int* ei) {
    if (threadIdx.x == 0) {
        int ok64 = 1;
        for (int i = 1; i < 256; i += 2)
            if (ei[i] != 0) { ok64 = 0; break; }
        d_is64 = ok64;
    }
}

// -------- split fp32 -> (hi, lo) fp16 pair;  n % 4 == 0 --------
__global__ void convert_split_kernel(const float* __restrict__ src,
                                     __half* __restrict__ hi,
                                     __half* __restrict__ lo, int n4) {
    int i = blockIdx.x * blockDim.x + threadIdx.x;
    if (i >= n4) return;
    float4 v = ((const float4*)src)[i];
    __half h0 = __float2half_rn(v.x), h1 = __float2half_rn(v.y);
    __half h2 = __float2half_rn(v.z), h3 = __float2half_rn(v.w);
    ((__half2*)hi)[2 * i]     = __halves2half2(h0, h1);
    ((__half2*)hi)[2 * i + 1] = __halves2half2(h2, h3);
    ((__half2*)lo)[2 * i]     = __floats2half2_rn(v.x - __half2float(h0),
                                                  v.y - __half2float(h1));
    ((__half2*)lo)[2 * i + 1] = __floats2half2_rn(v.z - __half2float(h2),
                                                  v.w - __half2float(h3));
}

// -------- CSR build --------
__global__ void count_kernel(const void* __restrict__ ei) {
    int tid = blockIdx.x * blockDim.x + threadIdx.x;
    if (tid >= EN) return;
    int s, d;
    load_edge(ei, d_is64, tid, s, d);
    atomicAdd(&d_cnt[d], 1);
}

__global__ void scanA_kernel() {
    __shared__ int sh[256];
    const int t = threadIdx.x;
    const int idx = blockIdx.x * 256 + t;
    int v = (idx < NN) ? d_cnt[idx] : 0;
    sh[t] = v;
    __syncthreads();
    #pragma unroll
    for (int o = 1; o < 256; o <<= 1) {
        int u = (t >= o) ? sh[t - o] : 0;
        __syncthreads();
        sh[t] += u;
        __syncthreads();
    }
    if (idx < NN) d_off[idx] = sh[t] - v;
    if (t == 255) d_bsum[blockIdx.x] = sh[255];
}

__global__ void scanB_kernel() {
    __shared__ int sh[64];
    const int t = threadIdx.x;
    int v = (t < SCAN_BLKS) ? d_bsum[t] : 0;
    sh[t] = v;
    __syncthreads();
    #pragma unroll
    for (int o = 1; o < 64; o <<= 1) {
        int u = (t >= o) ? sh[t - o] : 0;
        __syncthreads();
        sh[t] += u;
        __syncthreads();
    }
    if (t < SCAN_BLKS) d_bsum[t] = sh[t] - v;
    if (t == 63) d_off[NN] = sh[63];
}

__global__ void scanC_kernel() {
    int idx = blockIdx.x * 256 + threadIdx.x;
    if (idx < NN) d_off[idx] += d_bsum[blockIdx.x];
}

__global__ void fill_kernel(const void* __restrict__ ei) {
    int tid = blockIdx.x * blockDim.x + threadIdx.x;
    if (tid >= EN) return;
    int s, d;
    load_edge(ei, d_is64, tid, s, d);
    int pos = atomicSub(&d_cnt[d], 1) - 1;
    d_src_csr[d_off[d] + pos] = s;
}

// -------- split-fp16 tensor-core GEMM, cp.async 2-stage pipeline --------
// C = Ah@Bh + Ah@Bl + Al@Bh (fp32 acc). Inputs pre-split fp16 hi/lo.
// Tile: BM=64, BN=64, BK=32. 128 threads = 4 warps (2x2 grid of 32x32 tiles).
static constexpr int LDA_S = 40;   // 32 + 8 pad (halfs); 80 B row = 16B-aligned
static constexpr int LDB_S = 72;   // 64 + 8 pad (halfs); 144 B row = 16B-aligned
static constexpr int LDC_S = 68;   // 64 + 4 pad (floats)
static constexpr int ABUF = 64 * LDA_S;                 // halfs
static constexpr int BBUF = 32 * LDB_S;                 // halfs
static constexpr int STG  = 2 * ABUF + 2 * BBUF;        // halfs per stage (9728)

__global__ void __launch_bounds__(128) gemm_wmma(
        const __half* __restrict__ Ah, const __half* __restrict__ Al,
        const __half* __restrict__ Bh, const __half* __restrict__ Bl,
        const float* __restrict__ bias,
        __half* __restrict__ Oh, __half* __restrict__ Ol,
        int M, int N, int K, int do_relu) {
    __shared__ __align__(16) __half smh[2 * STG];       // 38912 B

    const int t   = threadIdx.x;
    const int wid = t >> 5;
    const int wm  = wid >> 1;         // 0..1
    const int wn  = wid & 1;          // 0..1
    const int m0  = blockIdx.y * 64;
    const int n0  = blockIdx.x * 64;
    const int nt  = K / 32;

    const uint32_t smbase = (uint32_t)__cvta_generic_to_shared(smh);

    // async loaders: 16B chunks. A tile: 64x32 halfs = 256 chunks; 2/thread.
    // B tile: 32x64 halfs = 256 chunks; 2/thread.
    auto load_tile = [&](int k0, int stg) {
        const uint32_t sb = smbase + stg * STG * 2;     // bytes
        #pragma unroll
        for (int i = 0; i < 2; i++) {
            int c = t + i * 128;
            {   // A hi/lo
                int row = c >> 2, col = (c & 3) * 8;
                bool ok = (m0 + row) < M;
                size_t go = (size_t)(m0 + row) * K + k0 + col;
                uint32_t so = sb + (row * LDA_S + col) * 2;
                cp16(so, Ah + go, ok);
                cp16(so + ABUF * 2, Al + go, ok);
            }
            {   // B hi/lo
                int row = c >> 3, col = (c & 7) * 8;
                size_t go = (size_t)(k0 + row) * N + n0 + col;
                uint32_t so = sb + (2 * ABUF + row * LDB_S + col) * 2;
                cp16(so, Bh + go, true);
                cp16(so + BBUF * 2, Bl + go, true);
            }
        }
    };

    load_tile(0, 0);
    cp_commit();

    wmma::fragment<wmma::accumulator, 16, 16, 16, float> acc[2][2];
    #pragma unroll
    for (int i = 0; i < 2; i++)
        #pragma unroll
        for (int j = 0; j < 2; j++)
            wmma::fill_fragment(acc[i][j], 0.f);

    cp_wait0();
    __syncthreads();

    for (int tile = 0; tile < nt; tile++) {
        const int cur = tile & 1;
        if (tile + 1 < nt) {
            load_tile((tile + 1) * 32, cur ^ 1);
            cp_commit();
        }

        const __half* Ash = smh + cur * STG;
        const __half* Asl = Ash + ABUF;
        const __half* Bsh = smh + cur * STG + 2 * ABUF;
        const __half* Bsl = Bsh + BBUF;

        #pragma unroll
        for (int kk = 0; kk < 32; kk += 16) {
            wmma::fragment<wmma::matrix_b, 16, 16, 16, __half, wmma::row_major> bfh[2], bfl[2];
            #pragma unroll
            for (int ni = 0; ni < 2; ni++) {
                wmma::load_matrix_sync(bfh[ni], Bsh + kk * LDB_S + wn * 32 + ni * 16, LDB_S);
                wmma::load_matrix_sync(bfl[ni], Bsl + kk * LDB_S + wn * 32 + ni * 16, LDB_S);
            }
            #pragma unroll
            for (int mi = 0; mi < 2; mi++) {
                wmma::fragment<wmma::matrix_a, 16, 16, 16, __half, wmma::row_major> afh, afl;
                const int ro = (wm * 32 + mi * 16) * LDA_S + kk;
                wmma::load_matrix_sync(afh, Ash + ro, LDA_S);
                wmma::load_matrix_sync(afl, Asl + ro, LDA_S);
                #pragma unroll
                for (int ni = 0; ni < 2; ni++) {
                    wmma::mma_sync(acc[mi][ni], afh, bfh[ni], acc[mi][ni]);
                    wmma::mma_sync(acc[mi][ni], afh, bfl[ni], acc[mi][ni]);
                    wmma::mma_sync(acc[mi][ni], afl, bfh[ni], acc[mi][ni]);
                }
            }
        }

        if (tile + 1 < nt) cp_wait0();
        __syncthreads();
    }

    // stage fp32 results to smem (overlays tile buffers; MMAs done)
    float* Cf = (float*)smh;
    #pragma unroll
    for (int mi = 0; mi < 2; mi++)
        #pragma unroll
        for (int ni = 0; ni < 2; ni++)
            wmma::store_matrix_sync(
                &Cf[(wm * 32 + mi * 16) * LDC_S + wn * 32 + ni * 16],
                acc[mi][ni], LDC_S, wmma::mem_row_major);
    __syncthreads();

    // epilogue: 128 threads, 32 outputs each
    {
        const int row = t >> 1;
        const int c0  = (t & 1) * 32;
        if (m0 + row < M) {
            #pragma unroll
            for (int j = 0; j < 32; j += 2) {
                float v0 = Cf[row * LDC_S + c0 + j];
                float v1 = Cf[row * LDC_S + c0 + j + 1];
                if (bias) {
                    v0 += bias[n0 + c0 + j];
                    v1 += bias[n0 + c0 + j + 1];
                }
                if (do_relu) { v0 = fmaxf(v0, 0.f); v1 = fmaxf(v1, 0.f); }
                __half h0 = __float2half_rn(v0), h1 = __float2half_rn(v1);
                size_t o = (size_t)(m0 + row) * N + n0 + c0 + j;
                *(__half2*)&Oh[o] = __halves2half2(h0, h1);
                if (Ol)
                    *(__half2*)&Ol[o] = __floats2half2_rn(
                        v0 - __half2float(h0), v1 - __half2float(h1));
            }
        }
    }
}

// -------- attention coefficients from fp16 g: one warp per (node, head) ----
__global__ void attn_coef_kernel(const float* __restrict__ att_src,
                                 const float* __restrict__ att_dst) {
    int warp = (blockIdx.x * blockDim.x + threadIdx.x) >> 5;
    int lane = threadIdx.x & 31;
    if (warp >= NN * HEADS) return;
    int n = warp / HEADS, h = warp % HEADS;
    const __half2* gp = (const __half2*)(d_g16 + (size_t)n * FEAT + h * GC);
    float2 gv = __half22float2(gp[lane]);
    float ss = gv.x * att_src[h * GC + 2 * lane] +
               gv.y * att_src[h * GC + 2 * lane + 1];
    float sd = gv.x * att_dst[h * GC + 2 * lane] +
               gv.y * att_dst[h * GC + 2 * lane + 1];
    #pragma unroll
    for (int o = 16; o; o >>= 1) {
        ss += __shfl_xor_sync(0xFFFFFFFFu, ss, o);
        sd += __shfl_xor_sync(0xFFFFFFFFu, sd, o);
    }
    if (lane == 0) {
        d_asrc[n * HEADS + h] = ss;
        d_adst[n * HEADS + h] = sd;
    }
}

// -------- gather aggregation: two-pass, fp16 features in pass 2 --------
__global__ void __launch_bounds__(256) gather_kernel(float* __restrict__ out,
                                                     const float* __restrict__ bias_g) {
    __shared__ float s_ex[4][MAXDEG * HEADS];
    __shared__ int   s_src[4][MAXDEG];

    const int grp  = threadIdx.x >> 6;
    const int t    = threadIdx.x & 63;
    const int node = blockIdx.x * 4 + grp;
    const int h    = t >> 4;
    const int l16  = t & 15;

    const int beg = d_off[node];
    const int deg = d_off[node + 1] - beg;
    const int cached = (deg < MAXDEG) ? deg : MAXDEG;

    for (int j = t; j < cached; j += 64)
        s_src[grp][j] = d_src_csr[beg + j];
    __syncthreads();

    const float adst_h = d_adst[node * HEADS + h];

    float psum = 0.f;
    for (int j = l16; j < deg; j += 16) {
        int s = (j < MAXDEG) ? s_src[grp][j] : d_src_csr[beg + j];
        float e = d_asrc[s * HEADS + h] + adst_h;
        e = (e > 0.f) ? e : NEG_SLOPE * e;
        float ex = __expf(e);
        if (j < MAXDEG) s_ex[grp][j * HEADS + h] = ex;
        psum += ex;
    }
    #pragma unroll
    for (int o = 8; o; o >>= 1)
        psum += __shfl_xor_sync(0xFFFFFFFFu, psum, o);
    const float inv = __frcp_rn(psum);
    __syncthreads();

    float4 acc = make_float4(0.f, 0.f, 0.f, 0.f);
    #pragma unroll 8
    for (int j = 0; j < cached; j++) {
        float alpha = s_ex[grp][j * HEADS + h] * inv;
        int s = s_src[grp][j];
        const __half2* gp = (const __half2*)&d_g16[(size_t)s * FEAT + 4 * t];
        float2 f01 = __half22float2(gp[0]);
        float2 f23 = __half22float2(gp[1]);
        acc.x = fmaf(f01.x, alpha, acc.x);
        acc.y = fmaf(f01.y, alpha, acc.y);
        acc.z = fmaf(f23.x, alpha, acc.z);
        acc.w = fmaf(f23.y, alpha, acc.w);
    }
    for (int j = cached; j < deg; j++) {
        int s = d_src_csr[beg + j];
        float e = d_asrc[s * HEADS + h] + adst_h;
        e = (e > 0.f) ? e : NEG_SLOPE * e;
        float alpha = __expf(e) * inv;
        const __half2* gp = (const __half2*)&d_g16[(size_t)s * FEAT + 4 * t];
        float2 f01 = __half22float2(gp[0]);
        float2 f23 = __half22float2(gp[1]);
        acc.x = fmaf(f01.x, alpha, acc.x);
        acc.y = fmaf(f01.y, alpha, acc.y);
        acc.z = fmaf(f23.x, alpha, acc.z);
        acc.w = fmaf(f23.y, alpha, acc.w);
    }

    float4 bv = *(const float4*)&bias_g[4 * t];
    acc.x += bv.x; acc.y += bv.y; acc.z += bv.z; acc.w += bv.w;
    *(float4*)&out[(size_t)node * FEAT + 4 * t] = acc;
}

// ----------------------------------------------------------------------------
extern "C" void kernel_launch(void* const* d_in, const int* in_sizes, int n_in,
                              void* d_out, int out_size) {
    const float* x        = (const float*)d_in[0];
    const void*  ei       = d_in[1];
    const float* W1       = (const float*)d_in[2];
    const float* b1       = (const float*)d_in[3];
    const float* W2       = (const float*)d_in[4];
    const float* b2       = (const float*)d_in[5];
    const float* Wg       = (const float*)d_in[6];
    const float* att_src  = (const float*)d_in[7];
    const float* att_dst  = (const float*)d_in[8];
    const float* bias_g   = (const float*)d_in[9];
    float* out = (float*)d_out;

    void *p_xh, *p_xl, *p_w1h, *p_w1l, *p_w2h, *p_w2l, *p_wgh, *p_wgl;
    void *p_h1h, *p_h1l, *p_h2h, *p_h2l, *p_g16;
    cudaGetSymbolAddress(&p_xh, d_xh);   cudaGetSymbolAddress(&p_xl, d_xl);
    cudaGetSymbolAddress(&p_w1h, d_w1h); cudaGetSymbolAddress(&p_w1l, d_w1l);
    cudaGetSymbolAddress(&p_w2h, d_w2h); cudaGetSymbolAddress(&p_w2l, d_w2l);
    cudaGetSymbolAddress(&p_wgh, d_wgh); cudaGetSymbolAddress(&p_wgl, d_wgl);
    cudaGetSymbolAddress(&p_h1h, d_h1h); cudaGetSymbolAddress(&p_h1l, d_h1l);
    cudaGetSymbolAddress(&p_h2h, d_h2h); cudaGetSymbolAddress(&p_h2l, d_h2l);
    cudaGetSymbolAddress(&p_g16, d_g16);

    setup_kernel<<<1, 32>>>((const int*)ei);                             // 0
    {   // 1: split x
        int n4 = NN * IND / 4;
        convert_split_kernel<<<(n4 + 255) / 256, 256>>>(
            x, (__half*)p_xh, (__half*)p_xl, n4);
    }
    {   // 2: split W1
        int n4 = IND * HIDD / 4;
        convert_split_kernel<<<(n4 + 255) / 256, 256>>>(
            W1, (__half*)p_w1h, (__half*)p_w1l, n4);
    }
    {   // 3 (profiled): GEMM1  h1 = relu(x@W1 + b1)
        dim3 grid(HIDD / 64, (NN + 63) / 64);
        gemm_wmma<<<grid, 128>>>((const __half*)p_xh, (const __half*)p_xl,
                                 (const __half*)p_w1h, (const __half*)p_w1l,
                                 b1, (__half*)p_h1h, (__half*)p_h1l,
                                 NN, HIDD, IND, 1);
    }
    {   // 4: split W2
        int n4 = HIDD * OUTD / 4;
        convert_split_kernel<<<(n4 + 255) / 256, 256>>>(
            W2, (__half*)p_w2h, (__half*)p_w2l, n4);
    }
    {   // 5: split Wg
        int n4 = OUTD * FEAT / 4;
        convert_split_kernel<<<(n4 + 255) / 256, 256>>>(
            Wg, (__half*)p_wgh, (__half*)p_wgl, n4);
    }
    count_kernel<<<(EN + 255) / 256, 256>>>(ei);                         // 6
    scanA_kernel<<<SCAN_BLKS, 256>>>();                                  // 7
    scanB_kernel<<<1, 64>>>();                                           // 8
    scanC_kernel<<<SCAN_BLKS, 256>>>();                                  // 9
    fill_kernel<<<(EN + 255) / 256, 256>>>(ei);                          // 10
    {   // 11: GEMM2  h2 = h1@W2 + b2
        dim3 grid(OUTD / 64, (NN + 63) / 64);
        gemm_wmma<<<grid, 128>>>((const __half*)p_h1h, (const __half*)p_h1l,
                                 (const __half*)p_w2h, (const __half*)p_w2l,
                                 b2, (__half*)p_h2h, (__half*)p_h2l,
                                 NN, OUTD, HIDD, 0);
    }
    {   // 12: GEMM3  g = h2@Wg  (hi only out)
        dim3 grid(FEAT / 64, (NN + 63) / 64);
        gemm_wmma<<<grid, 128>>>((const __half*)p_h2h, (const __half*)p_h2l,
                                 (const __half*)p_wgh, (const __half*)p_wgl,
                                 nullptr, (__half*)p_g16, nullptr,
                                 NN, FEAT, OUTD, 0);
    }
    {   // 13
        int warps = NN * HEADS;
        attn_coef_kernel<<<(warps * 32 + 255) / 256, 256>>>(att_src, att_dst);
    }
    gather_kernel<<<NN / 4, 256>>>(out, bias_g);                         // 14
}

// round 14
// speedup vs baseline: 1.1213x; 1.0477x over previous
#include <cuda_runtime.h>
#include <cuda_fp16.h>
#include <mma.h>
#include <math.h>
#include <cstdint>

using namespace nvcuda;

// Problem constants
static constexpr int NN   = 10000;
static constexpr int EE   = 320000;
static constexpr int EN   = EE + NN;        // edges + self loops
static constexpr int IND  = 512;
static constexpr int HIDD = 128;
static constexpr int OUTD = 128;
static constexpr int HEADS = 4;
static constexpr int GC    = 64;
static constexpr int FEAT  = HEADS * GC;    // 256
static constexpr float NEG_SLOPE = 0.2f;
static constexpr int MAXDEG = 256;

// convert segments (in float4 units)
static constexpr int X4  = NN * IND / 4;      // 1,280,000
static constexpr int W14 = IND * HIDD / 4;    // 16,384
static constexpr int W24 = HIDD * OUTD / 4;   // 4,096
static constexpr int WG4 = OUTD * FEAT / 4;   // 8,192
static constexpr int CV4 = X4 + W14 + W24 + WG4;

// -------- scratch (device globals: no allocation allowed) --------
__device__ __half d_xh [(size_t)NN * IND];
__device__ __half d_xl [(size_t)NN * IND];
__device__ __half d_w1h[IND * HIDD];
__device__ __half d_w1l[IND * HIDD];
__device__ __half d_w2h[HIDD * OUTD];
__device__ __half d_w2l[HIDD * OUTD];
__device__ __half d_wgh[OUTD * FEAT];
__device__ __half d_wgl[OUTD * FEAT];
__device__ __half d_h1h[(size_t)NN * HIDD];
__device__ __half d_h1l[(size_t)NN * HIDD];
__device__ __half d_h2h[(size_t)NN * OUTD];
__device__ __half d_h2l[(size_t)NN * OUTD];
__device__ __half d_g16[(size_t)NN * FEAT];
__device__ float  d_asrc[NN * HEADS];
__device__ float  d_adst[NN * HEADS];
__device__ int    d_cnt[NN];          // zero-init; count fills, fill drains to 0
__device__ int    d_off[NN + 1];
__device__ int    d_src_csr[EN];
__device__ int    d_is64;

// -------- helpers --------
__device__ __forceinline__ void load_edge(const void* ei, int is64, int tid,
                                          int& s, int& d) {
    if (tid < EE) {
        if (is64) {
            const long long* p = (const long long*)ei;
            s = (int)p[tid];
            d = (int)p[EE + tid];
        } else {
            const int* p = (const int*)ei;
            s = p[tid];
            d = p[EE + tid];
        }
    } else {
        s = d = tid - EE;
    }
}

__device__ __forceinline__ void cp16(uint32_t smem_dst, const void* gsrc, bool pred) {
    int sz = pred ? 16 : 0;
    asm volatile("cp.async.ca.shared.global [%0], [%1], 16, %2;\n"
                 :: "r"(smem_dst), "l"(gsrc), "r"(sz));
}
__device__ __forceinline__ void cp_commit() {
    asm volatile("cp.async.commit_group;\n");
}
__device__ __forceinline__ void cp_wait0() {
    asm volatile("cp.async.wait_group 0;\n");
}

// -------- setup: detect int64 vs int32 edge_index --------
__global__ void setup_kernel(const int* ei) {
    if (threadIdx.x == 0) {
        int ok64 = 1;
        for (int i = 1; i < 256; i += 2)
            if (ei[i] != 0) { ok64 = 0; break; }
        d_is64 = ok64;
    }
}

// -------- merged split-convert for x, W1, W2, Wg --------
__global__ void convert_all_kernel(const float* __restrict__ x,
                                   const float* __restrict__ W1,
                                   const float* __restrict__ W2,
                                   const float* __restrict__ Wg) {
    int i = blockIdx.x * blockDim.x + threadIdx.x;
    if (i >= CV4) return;
    const float* src;
    __half *hi, *lo;
    int off;
    if (i < X4)                  { src = x;  hi = d_xh;  lo = d_xl;  off = i; }
    else if (i < X4 + W14)       { src = W1; hi = d_w1h; lo = d_w1l; off = i - X4; }
    else if (i < X4 + W14 + W24) { src = W2; hi = d_w2h; lo = d_w2l; off = i - X4 - W14; }
    else                         { src = Wg; hi = d_wgh; lo = d_wgl; off = i - X4 - W14 - W24; }
    float4 v = ((const float4*)src)[off];
    __half h0 = __float2half_rn(v.x), h1 = __float2half_rn(v.y);
    __half h2 = __float2half_rn(v.z), h3 = __float2half_rn(v.w);
    ((__half2*)hi)[2 * off]     = __halves2half2(h0, h1);
    ((__half2*)hi)[2 * off + 1] = __halves2half2(h2, h3);
    ((__half2*)lo)[2 * off]     = __floats2half2_rn(v.x - __half2float(h0),
                                                    v.y - __half2float(h1));
    ((__half2*)lo)[2 * off + 1] = __floats2half2_rn(v.z - __half2float(h2),
                                                    v.w - __half2float(h3));
}

// -------- CSR build --------
__global__ void count_kernel(const void* __restrict__ ei) {
    int tid = blockIdx.x * blockDim.x + threadIdx.x;
    if (tid >= EN) return;
    int s, d;
    load_edge(ei, d_is64, tid, s, d);
    atomicAdd(&d_cnt[d], 1);
}

// single-block exclusive scan: 1024 threads, 10 elems each (contiguous)
static constexpr int SCH = 10;   // 1024*10 = 10240 >= NN
__global__ void scan_kernel() {
    __shared__ int wsum[32];
    const int t    = threadIdx.x;
    const int lane = t & 31;
    const int wid  = t >> 5;
    const int base = t * SCH;

    int vals[SCH];
    int s = 0;
    #pragma unroll
    for (int i = 0; i < SCH; i++) {
        int idx = base + i;
        int v = (idx < NN) ? d_cnt[idx] : 0;
        vals[i] = s;          // local exclusive prefix
        s += v;
    }
    // inclusive warp scan of per-thread totals
    int ws = s;
    #pragma unroll
    for (int o = 1; o < 32; o <<= 1) {
        int u = __shfl_up_sync(0xFFFFFFFFu, ws, o);
        if (lane >= o) ws += u;
    }
    if (lane == 31) wsum[wid] = ws;
    __syncthreads();
    if (wid == 0) {
        int w = (lane < 32) ? wsum[lane] : 0;
        int iw = w;
        #pragma unroll
        for (int o = 1; o < 32; o <<= 1) {
            int u = __shfl_up_sync(0xFFFFFFFFu, iw, o);
            if (lane >= o) iw += u;
        }
        wsum[lane] = iw - w;  // exclusive warp offsets
    }
    __syncthreads();
    int thr_off = wsum[wid] + ws - s;   // exclusive offset of this thread
    #pragma unroll
    for (int i = 0; i < SCH; i++) {
        int idx = base + i;
        if (idx < NN) d_off[idx] = thr_off + vals[i];
    }
    if (t == 1023) d_off[NN] = wsum[31] + ws;   // == thr_off + s for last thread
}

__global__ void fill_kernel(const void* __restrict__ ei) {
    int tid = blockIdx.x * blockDim.x + threadIdx.x;
    if (tid >= EN) return;
    int s, d;
    load_edge(ei, d_is64, tid, s, d);
    int pos = atomicSub(&d_cnt[d], 1) - 1;
    d_src_csr[d_off[d] + pos] = s;
}

// -------- split-fp16 tensor-core GEMM, cp.async 2-stage, term-outer MMA ----
// C = Ah@Bh + Ah@Bl + Al@Bh (fp32 acc). Inputs pre-split fp16 hi/lo.
// Tile: BM=64, BN=64, BK=32. 128 threads = 4 warps (2x2 grid of 32x32 tiles).
static constexpr int LDA_S = 40;
static constexpr int LDB_S = 72;
static constexpr int LDC_S = 68;
static constexpr int ABUF = 64 * LDA_S;
static constexpr int BBUF = 32 * LDB_S;
static constexpr int STG  = 2 * ABUF + 2 * BBUF;

__global__ void __launch_bounds__(128) gemm_wmma(
        const __half* __restrict__ Ah, const __half* __restrict__ Al,
        const __half* __restrict__ Bh, const __half* __restrict__ Bl,
        const float* __restrict__ bias,
        __half* __restrict__ Oh, __half* __restrict__ Ol,
        int M, int N, int K, int do_relu) {
    __shared__ __align__(16) __half smh[2 * STG];

    const int t   = threadIdx.x;
    const int wid = t >> 5;
    const int wm  = wid >> 1;
    const int wn  = wid & 1;
    const int m0  = blockIdx.y * 64;
    const int n0  = blockIdx.x * 64;
    const int nt  = K / 32;

    const uint32_t smbase = (uint32_t)__cvta_generic_to_shared(smh);

    auto load_tile = [&](int k0, int stg) {
        const uint32_t sb = smbase + stg * STG * 2;
        #pragma unroll
        for (int i = 0; i < 2; i++) {
            int c = t + i * 128;
            {   // A hi/lo
                int row = c >> 2, col = (c & 3) * 8;
                bool ok = (m0 + row) < M;
                size_t go = (size_t)(m0 + row) * K + k0 + col;
                uint32_t so = sb + (row * LDA_S + col) * 2;
                cp16(so, Ah + go, ok);
                cp16(so + ABUF * 2, Al + go, ok);
            }
            {   // B hi/lo
                int row = c >> 3, col = (c & 7) * 8;
                size_t go = (size_t)(k0 + row) * N + n0 + col;
                uint32_t so = sb + (2 * ABUF + row * LDB_S + col) * 2;
                cp16(so, Bh + go, true);
                cp16(so + BBUF * 2, Bl + go, true);
            }
        }
    };

    load_tile(0, 0);
    cp_commit();

    wmma::fragment<wmma::accumulator, 16, 16, 16, float> acc[2][2];
    #pragma unroll
    for (int i = 0; i < 2; i++)
        #pragma unroll
        for (int j = 0; j < 2; j++)
            wmma::fill_fragment(acc[i][j], 0.f);

    cp_wait0();
    __syncthreads();

    for (int tile = 0; tile < nt; tile++) {
        const int cur = tile & 1;
        if (tile + 1 < nt) {
            load_tile((tile + 1) * 32, cur ^ 1);
            cp_commit();
        }

        const __half* Ash = smh + cur * STG;
        const __half* Asl = Ash + ABUF;
        const __half* Bsh = smh + cur * STG + 2 * ABUF;
        const __half* Bsl = Bsh + BBUF;

        #pragma unroll
        for (int kk = 0; kk < 32; kk += 16) {
            wmma::fragment<wmma::matrix_a, 16, 16, 16, __half, wmma::row_major> afh[2], afl[2];
            wmma::fragment<wmma::matrix_b, 16, 16, 16, __half, wmma::row_major> bfh[2], bfl[2];
            #pragma unroll
            for (int ni = 0; ni < 2; ni++) {
                wmma::load_matrix_sync(bfh[ni], Bsh + kk * LDB_S + wn * 32 + ni * 16, LDB_S);
                wmma::load_matrix_sync(bfl[ni], Bsl + kk * LDB_S + wn * 32 + ni * 16, LDB_S);
            }
            #pragma unroll
            for (int mi = 0; mi < 2; mi++) {
                const int ro = (wm * 32 + mi * 16) * LDA_S + kk;
                wmma::load_matrix_sync(afh[mi], Ash + ro, LDA_S);
                wmma::load_matrix_sync(afl[mi], Asl + ro, LDA_S);
            }
            // term-outer: dependent MMAs to the same acc are 4 apart
            #pragma unroll
            for (int mi = 0; mi < 2; mi++)
                #pragma unroll
                for (int ni = 0; ni < 2; ni++)
                    wmma::mma_sync(acc[mi][ni], afh[mi], bfh[ni], acc[mi][ni]);
            #pragma unroll
            for (int mi = 0; mi < 2; mi++)
                #pragma unroll
                for (int ni = 0; ni < 2; ni++)
                    wmma::mma_sync(acc[mi][ni], afh[mi], bfl[ni], acc[mi][ni]);
            #pragma unroll
            for (int mi = 0; mi < 2; mi++)
                #pragma unroll
                for (int ni = 0; ni < 2; ni++)
                    wmma::mma_sync(acc[mi][ni], afl[mi], bfh[ni], acc[mi][ni]);
        }

        if (tile + 1 < nt) cp_wait0();
        __syncthreads();
    }

    float* Cf = (float*)smh;
    #pragma unroll
    for (int mi = 0; mi < 2; mi++)
        #pragma unroll
        for (int ni = 0; ni < 2; ni++)
            wmma::store_matrix_sync(
                &Cf[(wm * 32 + mi * 16) * LDC_S + wn * 32 + ni * 16],
                acc[mi][ni], LDC_S, wmma::mem_row_major);
    __syncthreads();

    {
        const int row = t >> 1;
        const int c0  = (t & 1) * 32;
        if (m0 + row < M) {
            #pragma unroll
            for (int j = 0; j < 32; j += 2) {
                float v0 = Cf[row * LDC_S + c0 + j];
                float v1 = Cf[row * LDC_S + c0 + j + 1];
                if (bias) {
                    v0 += bias[n0 + c0 + j];
                    v1 += bias[n0 + c0 + j + 1];
                }
                if (do_relu) { v0 = fmaxf(v0, 0.f); v1 = fmaxf(v1, 0.f); }
                __half h0 = __float2half_rn(v0), h1 = __float2half_rn(v1);
                size_t o = (size_t)(m0 + row) * N + n0 + c0 + j;
                *(__half2*)&Oh[o] = __halves2half2(h0, h1);
                if (Ol)
                    *(__half2*)&Ol[o] = __floats2half2_rn(
                        v0 - __half2float(h0), v1 - __half2float(h1));
            }
        }
    }
}

// -------- attention coefficients from fp16 g: one warp per (node, head) ----
__global__ void attn_coef_kernel(const float* __restrict__ att_src,
                                 const float* __restrict__ att_dst) {
    int warp = (blockIdx.x * blockDim.x + threadIdx.x) >> 5;
    int lane = threadIdx.x & 31;
    if (warp >= NN * HEADS) return;
    int n = warp / HEADS, h = warp % HEADS;
    const __half2* gp = (const __half2*)(d_g16 + (size_t)n * FEAT + h * GC);
    float2 gv = __half22float2(gp[lane]);
    float ss = gv.x * att_src[h * GC + 2 * lane] +
               gv.y * att_src[h * GC + 2 * lane + 1];
    float sd = gv.x * att_dst[h * GC + 2 * lane] +
               gv.y * att_dst[h * GC + 2 * lane + 1];
    #pragma unroll
    for (int o = 16; o; o >>= 1) {
        ss += __shfl_xor_sync(0xFFFFFFFFu, ss, o);
        sd += __shfl_xor_sync(0xFFFFFFFFu, sd, o);
    }
    if (lane == 0) {
        d_asrc[n * HEADS + h] = ss;
        d_adst[n * HEADS + h] = sd;
    }
}

// -------- gather aggregation: two-pass, fp16 features in pass 2 --------
__global__ void __launch_bounds__(256) gather_kernel(float* __restrict__ out,
                                                     const float* __restrict__ bias_g) {
    __shared__ float s_ex[4][MAXDEG * HEADS];
    __shared__ int   s_src[4][MAXDEG];

    const int grp  = threadIdx.x >> 6;
    const int t    = threadIdx.x & 63;
    const int node = blockIdx.x * 4 + grp;
    const int h    = t >> 4;
    const int l16  = t & 15;

    const int beg = d_off[node];
    const int deg = d_off[node + 1] - beg;
    const int cached = (deg < MAXDEG) ? deg : MAXDEG;

    for (int j = t; j < cached; j += 64)
        s_src[grp][j] = d_src_csr[beg + j];
    __syncthreads();

    const float adst_h = d_adst[node * HEADS + h];

    float psum = 0.f;
    for (int j = l16; j < deg; j += 16) {
        int s = (j < MAXDEG) ? s_src[grp][j] : d_src_csr[beg + j];
        float e = d_asrc[s * HEADS + h] + adst_h;
        e = (e > 0.f) ? e : NEG_SLOPE * e;
        float ex = __expf(e);
        if (j < MAXDEG) s_ex[grp][j * HEADS + h] = ex;
        psum += ex;
    }
    #pragma unroll
    for (int o = 8; o; o >>= 1)
        psum += __shfl_xor_sync(0xFFFFFFFFu, psum, o);
    const float inv = __frcp_rn(psum);
    __syncthreads();

    float4 acc = make_float4(0.f, 0.f, 0.f, 0.f);
    #pragma unroll 8
    for (int j = 0; j < cached; j++) {
        float alpha = s_ex[grp][j * HEADS + h] * inv;
        int s = s_src[grp][j];
        const __half2* gp = (const __half2*)&d_g16[(size_t)s * FEAT + 4 * t];
        float2 f01 = __half22float2(gp[0]);
        float2 f23 = __half22float2(gp[1]);
        acc.x = fmaf(f01.x, alpha, acc.x);
        acc.y = fmaf(f01.y, alpha, acc.y);
        acc.z = fmaf(f23.x, alpha, acc.z);
        acc.w = fmaf(f23.y, alpha, acc.w);
    }
    for (int j = cached; j < deg; j++) {
        int s = d_src_csr[beg + j];
        float e = d_asrc[s * HEADS + h] + adst_h;
        e = (e > 0.f) ? e : NEG_SLOPE * e;
        float alpha = __expf(e) * inv;
        const __half2* gp = (const __half2*)&d_g16[(size_t)s * FEAT + 4 * t];
        float2 f01 = __half22float2(gp[0]);
        float2 f23 = __half22float2(gp[1]);
        acc.x = fmaf(f01.x, alpha, acc.x);
        acc.y = fmaf(f01.y, alpha, acc.y);
        acc.z = fmaf(f23.x, alpha, acc.z);
        acc.w = fmaf(f23.y, alpha, acc.w);
    }

    float4 bv = *(const float4*)&bias_g[4 * t];
    acc.x += bv.x; acc.y += bv.y; acc.z += bv.z; acc.w += bv.w;
    *(float4*)&out[(size_t)node * FEAT + 4 * t] = acc;
}

// ----------------------------------------------------------------------------
extern "C" void kernel_launch(void* const* d_in, const int* in_sizes, int n_in,
                              void* d_out, int out_size) {
    const float* x        = (const float*)d_in[0];
    const void*  ei       = d_in[1];
    const float* W1       = (const float*)d_in[2];
    const float* b1       = (const float*)d_in[3];
    const float* W2       = (const float*)d_in[4];
    const float* b2       = (const float*)d_in[5];
    const float* Wg       = (const float*)d_in[6];
    const float* att_src  = (const float*)d_in[7];
    const float* att_dst  = (const float*)d_in[8];
    const float* bias_g   = (const float*)d_in[9];
    float* out = (float*)d_out;

    void *p_xh, *p_xl, *p_w1h, *p_w1l, *p_w2h, *p_w2l, *p_wgh, *p_wgl;
    void *p_h1h, *p_h1l, *p_h2h, *p_h2l, *p_g16;
    cudaGetSymbolAddress(&p_xh, d_xh);   cudaGetSymbolAddress(&p_xl, d_xl);
    cudaGetSymbolAddress(&p_w1h, d_w1h); cudaGetSymbolAddress(&p_w1l, d_w1l);
    cudaGetSymbolAddress(&p_w2h, d_w2h); cudaGetSymbolAddress(&p_w2l, d_w2l);
    cudaGetSymbolAddress(&p_wgh, d_wgh); cudaGetSymbolAddress(&p_wgl, d_wgl);
    cudaGetSymbolAddress(&p_h1h, d_h1h); cudaGetSymbolAddress(&p_h1l, d_h1l);
    cudaGetSymbolAddress(&p_h2h, d_h2h); cudaGetSymbolAddress(&p_h2l, d_h2l);
    cudaGetSymbolAddress(&p_g16, d_g16);

    setup_kernel<<<1, 32>>>((const int*)ei);                             // 0
    convert_all_kernel<<<(CV4 + 255) / 256, 256>>>(x, W1, W2, Wg);       // 1
    count_kernel<<<(EN + 255) / 256, 256>>>(ei);                         // 2
    {   // 3 (profiled): GEMM1  h1 = relu(x@W1 + b1)
        dim3 grid(HIDD / 64, (NN + 63) / 64);
        gemm_wmma<<<grid, 128>>>((const __half*)p_xh, (const __half*)p_xl,
                                 (const __half*)p_w1h, (const __half*)p_w1l,
                                 b1, (__half*)p_h1h, (__half*)p_h1l,
                                 NN, HIDD, IND, 1);
    }
    scan_kernel<<<1, 1024>>>();                                          // 4
    fill_kernel<<<(EN + 255) / 256, 256>>>(ei);                          // 5
    {   // 6: GEMM2  h2 = h1@W2 + b2
        dim3 grid(OUTD / 64, (NN + 63) / 64);
        gemm_wmma<<<grid, 128>>>((const __half*)p_h1h, (const __half*)p_h1l,
                                 (const __half*)p_w2h, (const __half*)p_w2l,
                                 b2, (__half*)p_h2h, (__half*)p_h2l,
                                 NN, OUTD, HIDD, 0);
    }
    {   // 7: GEMM3  g = h2@Wg  (hi only out)
        dim3 grid(FEAT / 64, (NN + 63) / 64);
        gemm_wmma<<<grid, 128>>>((const __half*)p_h2h, (const __half*)p_h2l,
                                 (const __half*)p_wgh, (const __half*)p_wgl,
                                 nullptr, (__half*)p_g16, nullptr,
                                 NN, FEAT, OUTD, 0);
    }
    {   // 8
        int warps = NN * HEADS;
        attn_coef_kernel<<<(warps * 32 + 255) / 256, 256>>>(att_src, att_dst);
    }
    gather_kernel<<<NN / 4, 256>>>(out, bias_g);                         // 9
}